// round 14
// baseline (speedup 1.0000x reference)
#include <cuda_runtime.h>
#include <math.h>
#include <cstdint>

#define NPATCH 196
#define BLOCK  128   // 4 warps = 2 pairs; each pair handles 2 images -> 4 images/block

#define FMA_F32X2(d, a, b, c) \
    asm("fma.rn.f32x2 %0, %1, %2, %3;" : "=l"(d) : "l"(a), "l"(b), "l"(c))
#define PACK_F32X2(out, lo, hi) \
    asm("mov.b64 %0, {%1, %2};" : "=l"(out) : "f"(lo), "f"(hi))
#define UNPACK_F32X2(lo, hi, in) \
    asm("mov.b64 {%0, %1}, %2;" : "=f"(lo), "=f"(hi) : "l"(in))

__global__ __launch_bounds__(BLOCK, 4)   // reg cap 128; 512 blocks -> single wave
void quanv_fused_kernel(const float* __restrict__ x,
                        const float* __restrict__ emb_W,
                        const float* __restrict__ emb_b,
                        const float* __restrict__ q_params,
                        const float* __restrict__ lin_W,
                        const float* __restrict__ lin_b,
                        float* __restrict__ out,
                        int B)
{
    __shared__ float spart[2][2][2][10];   // [pair][h(writer)][img][chan]

    const int warp = threadIdx.x >> 5;     // 0..3
    const int lane = threadIdx.x & 31;
    const int pair = warp >> 1;
    const int h    = warp & 1;             // round-half id
    const int bA   = blockIdx.x * 4 + pair * 2;   // image A; image B = bA+1
    const bool vA  = (bA < B), vB = (bA + 1 < B);
    const int sA   = vA ? bA : 0, sB = vB ? (bA + 1) : 0;

    // ---- uniform circuit constants ----
    const float Kc0 = __cosf(q_params[0]);
    const float Kq1 = q_params[1];
    float s4, c4;
    __sincosf(q_params[4], &s4, &c4);
    const float Ks4 = s4 * __cosf(q_params[2]);
    const float Kc3 = __cosf(q_params[3]);

    const float4 W0 = __ldg((const float4*)(emb_W + 0));
    const float4 W1 = __ldg((const float4*)(emb_W + 4));
    const float4 W2 = __ldg((const float4*)(emb_W + 8));
    const float4 W3 = __ldg((const float4*)(emb_W + 12));
    const float4 eb = __ldg((const float4*)emb_b);

    const float*   xA  = x + sA * 784;
    const float*   xB  = x + sB * 784;
    const double2* lw2 = (const double2*)lin_W;

    // warp h owns rounds: h=0 -> {0,1,2,6(tail)} ; h=1 -> {3,4,5}
    const int nr = 4 - h;
    const bool tl = (lane < 4);

    // ---- phase A: front-batch x loads for BOTH images (MLP up to 16) ----
    float2 tpA[4], btA[4], tpB[4], btB[4];
#pragma unroll
    for (int r = 0; r < 4; r++) {
        if (r >= nr) break;                               // warp-uniform
        const int k = (h == 0) ? ((r < 3) ? r : 6) : (3 + r);
        const int p = (k < 6) ? (lane + 32 * k) : (192 + (tl ? lane : 0));
        const int pr = p / 14, pc = p % 14;
        const int o0 = (2 * pr) * 28 + 2 * pc, o1 = o0 + 28;
        tpA[r] = *(const float2*)(xA + o0);
        btA[r] = *(const float2*)(xA + o1);
        tpB[r] = *(const float2*)(xB + o0);
        btB[r] = *(const float2*)(xB + o1);
    }

    // ---- phase B: features for both images ----
    unsigned long long E01A[4], E23A[4], E01B[4], E23B[4];
#pragma unroll
    for (int r = 0; r < 4; r++) {
        if (r >= nr) break;                               // warp-uniform
        const int k = (h == 0) ? ((r < 3) ? r : 6) : (3 + r);
        const bool tail = (k == 6);
#pragma unroll
        for (int im = 0; im < 2; im++) {
            const float2 T  = im ? tpB[r] : tpA[r];
            const float2 Bt = im ? btB[r] : btA[r];
            const float a0 = fmaf(T.x, W0.x, fmaf(T.y, W0.y, fmaf(Bt.x, W0.z, fmaf(Bt.y, W0.w, eb.x))));
            const float a1 = fmaf(T.x, W1.x, fmaf(T.y, W1.y, fmaf(Bt.x, W1.z, fmaf(Bt.y, W1.w, eb.y))));
            const float a2 = fmaf(T.x, W2.x, fmaf(T.y, W2.y, fmaf(Bt.x, W2.z, fmaf(Bt.y, W2.w, eb.z))));
            const float a3 = fmaf(T.x, W3.x, fmaf(T.y, W3.y, fmaf(Bt.x, W3.z, fmaf(Bt.y, W3.w, eb.w))));

            const float ca0  = __cosf(a0);
            const float ca1q = __cosf(a1 + Kq1);
            float sa2, ca2, sa3, ca3;
            __sincosf(a2, &sa2, &ca2);
            __sincosf(a3, &sa3, &ca3);

            float e0 = Kc0 * ca0;
            float e1 = e0 * ca1q;
            float e2 = e1 * fmaf(c4, ca2, -Ks4 * sa2 * sa3);
            float e3 = ca2 * (Kc3 * ca3);
            if (tail && !tl) { e0 = 0.f; e1 = 0.f; e2 = 0.f; e3 = 0.f; }

            if (im) { PACK_F32X2(E01B[r], e0, e1); PACK_F32X2(E23B[r], e2, e3); }
            else    { PACK_F32X2(E01A[r], e0, e1); PACK_F32X2(E23A[r], e2, e3); }
        }
    }

    // ---- phase C: GEMV over this half's rounds; each weight load feeds 2 images ----
    float aA[10], aB[10];
#pragma unroll
    for (int c = 0; c < 10; c++) {
        unsigned long long accA = 0ull, accB = 0ull;
#pragma unroll
        for (int r = 0; r < 4; r++) {
            if (r >= nr) break;                           // warp-uniform
            const int k = (h == 0) ? ((r < 3) ? r : 6) : (3 + r);
            const int p = (k < 6) ? (lane + 32 * k) : (192 + (tl ? lane : 0));
            const double2 wd = __ldg(&lw2[c * NPATCH + p]);
            const unsigned long long wxy = __double_as_longlong(wd.x);
            const unsigned long long wzw = __double_as_longlong(wd.y);
            FMA_F32X2(accA, E23A[r], wzw, accA);
            FMA_F32X2(accA, E01A[r], wxy, accA);
            FMA_F32X2(accB, E23B[r], wzw, accB);
            FMA_F32X2(accB, E01B[r], wxy, accB);
        }
        float lo, hi;
        UNPACK_F32X2(lo, hi, accA); aA[c] = lo + hi;
        UNPACK_F32X2(lo, hi, accB); aB[c] = lo + hi;
    }

    // ---- split butterfly: one xor-16 step on all 20, then halves specialize ----
#pragma unroll
    for (int c = 0; c < 10; c++) {
        aA[c] += __shfl_xor_sync(0xffffffffu, aA[c], 16);
        aB[c] += __shfl_xor_sync(0xffffffffu, aB[c], 16);
    }
    const bool hiHalf = (lane >= 16);
    float v[10];
#pragma unroll
    for (int c = 0; c < 10; c++) v[c] = hiHalf ? aB[c] : aA[c];
#pragma unroll
    for (int off = 8; off > 0; off >>= 1)
#pragma unroll
        for (int c = 0; c < 10; c++)
            v[c] += __shfl_xor_sync(0xffffffffu, v[c], off);
    // lanes 0-15: image A channel sums; lanes 16-31: image B

    // handoff (predicated selection, no dynamic reg indexing)
    {
        const int sl = lane & 15;
        float w = v[0];
#pragma unroll
        for (int c = 1; c < 10; c++) if (sl == c) w = v[c];
        if (sl < 10) spart[pair][h][hiHalf ? 1 : 0][sl] = w;
    }
    __syncthreads();

    // ---- finalize: warp h finishes image h of its pair (balanced) ----
    const int  bO = bA + h;
    const bool vO = (h == 0) ? vA : vB;
    if (lane < 10 && vO) {
        float lg[10];
#pragma unroll
        for (int c = 0; c < 10; c++)
            lg[c] = spart[pair][0][h][c] + spart[pair][1][h][c] + __ldg(&lin_b[c]);

        float mx = lg[0];
#pragma unroll
        for (int c = 1; c < 10; c++) mx = fmaxf(mx, lg[c]);
        float se = 0.f;
#pragma unroll
        for (int c = 0; c < 10; c++) se += __expf(lg[c] - mx);
        const float lse = mx + __logf(se);

        float v2 = lg[0];
#pragma unroll
        for (int c = 1; c < 10; c++) if (lane == c) v2 = lg[c];
        out[bO * 10 + lane] = v2 - lse;
    }
}

extern "C" void kernel_launch(void* const* d_in, const int* in_sizes, int n_in,
                              void* d_out, int out_size)
{
    const float* x        = (const float*)d_in[0];
    const float* emb_W    = (const float*)d_in[1];
    const float* emb_b    = (const float*)d_in[2];
    const float* q_params = (const float*)d_in[3];
    const float* lin_W    = (const float*)d_in[4];
    const float* lin_b    = (const float*)d_in[5];
    float* out = (float*)d_out;

    const int B = in_sizes[0] / 784;
    const int grid = (B + 3) / 4;
    quanv_fused_kernel<<<grid, BLOCK>>>(x, emb_W, emb_b, q_params, lin_W, lin_b, out, B);
}

// round 15
// speedup vs baseline: 1.0037x; 1.0037x over previous
#include <cuda_runtime.h>
#include <math.h>
#include <cstdint>

#define NPATCH 196
#define BLOCK  128   // 4 warps = 2 pairs; each pair handles 2 images -> 4 images/block

#define FMA_F32X2(d, a, b, c) \
    asm("fma.rn.f32x2 %0, %1, %2, %3;" : "=l"(d) : "l"(a), "l"(b), "l"(c))
#define PACK_F32X2(out, lo, hi) \
    asm("mov.b64 %0, {%1, %2};" : "=l"(out) : "f"(lo), "f"(hi))
#define UNPACK_F32X2(lo, hi, in) \
    asm("mov.b64 {%0, %1}, %2;" : "=f"(lo), "=f"(hi) : "l"(in))

__global__ __launch_bounds__(BLOCK, 4)   // reg cap 128; 512 blocks -> single wave
void quanv_fused_kernel(const float* __restrict__ x,
                        const float* __restrict__ emb_W,
                        const float* __restrict__ emb_b,
                        const float* __restrict__ q_params,
                        const float* __restrict__ lin_W,
                        const float* __restrict__ lin_b,
                        float* __restrict__ out,
                        int B)
{
    __shared__ float spart[2][2][2][10];   // [pair][h(writer)][img][chan]

    const int warp = threadIdx.x >> 5;     // 0..3
    const int lane = threadIdx.x & 31;
    const int pair = warp >> 1;
    const int h    = warp & 1;             // round-half id
    const int bA   = blockIdx.x * 4 + pair * 2;   // image A; image B = bA+1
    const bool vA  = (bA < B), vB = (bA + 1 < B);
    const int sA   = vA ? bA : 0, sB = vB ? (bA + 1) : 0;

    // ---- uniform circuit constants ----
    const float Kc0 = __cosf(q_params[0]);
    const float Kq1 = q_params[1];
    float s4, c4;
    __sincosf(q_params[4], &s4, &c4);
    const float Ks4 = s4 * __cosf(q_params[2]);
    const float Kc3 = __cosf(q_params[3]);

    const float4 W0 = __ldg((const float4*)(emb_W + 0));
    const float4 W1 = __ldg((const float4*)(emb_W + 4));
    const float4 W2 = __ldg((const float4*)(emb_W + 8));
    const float4 W3 = __ldg((const float4*)(emb_W + 12));
    const float4 eb = __ldg((const float4*)emb_b);

    const float*   xA  = x + sA * 784;
    const float*   xB  = x + sB * 784;
    const double2* lw2 = (const double2*)lin_W;

    // warp h owns rounds: h=0 -> {0,1,2,6(tail)} ; h=1 -> {3,4,5}
    const int nr = 4 - h;
    const bool tl = (lane < 4);

    // ---- phase A: front-batch x loads for BOTH images (MLP up to 16) ----
    float2 tpA[4], btA[4], tpB[4], btB[4];
#pragma unroll
    for (int r = 0; r < 4; r++) {
        if (r >= nr) break;                               // warp-uniform
        const int k = (h == 0) ? ((r < 3) ? r : 6) : (3 + r);
        const int p = (k < 6) ? (lane + 32 * k) : (192 + (tl ? lane : 0));
        const int pr = p / 14, pc = p % 14;
        const int o0 = (2 * pr) * 28 + 2 * pc, o1 = o0 + 28;
        tpA[r] = *(const float2*)(xA + o0);
        btA[r] = *(const float2*)(xA + o1);
        tpB[r] = *(const float2*)(xB + o0);
        btB[r] = *(const float2*)(xB + o1);
    }

    // ---- fused per-round: features (both images) then immediate 10-channel GEMV ----
    unsigned long long acc2A[10], acc2B[10];
#pragma unroll
    for (int c = 0; c < 10; c++) { acc2A[c] = 0ull; acc2B[c] = 0ull; }

#pragma unroll
    for (int r = 0; r < 4; r++) {
        if (r >= nr) break;                               // warp-uniform
        const int k = (h == 0) ? ((r < 3) ? r : 6) : (3 + r);
        const bool tail = (k == 6);
        const int p = tail ? (192 + (tl ? lane : 0)) : (lane + 32 * k);

        unsigned long long E01A, E23A, E01B, E23B;
#pragma unroll
        for (int im = 0; im < 2; im++) {
            const float2 T  = im ? tpB[r] : tpA[r];
            const float2 Bt = im ? btB[r] : btA[r];
            const float a0 = fmaf(T.x, W0.x, fmaf(T.y, W0.y, fmaf(Bt.x, W0.z, fmaf(Bt.y, W0.w, eb.x))));
            const float a1 = fmaf(T.x, W1.x, fmaf(T.y, W1.y, fmaf(Bt.x, W1.z, fmaf(Bt.y, W1.w, eb.y))));
            const float a2 = fmaf(T.x, W2.x, fmaf(T.y, W2.y, fmaf(Bt.x, W2.z, fmaf(Bt.y, W2.w, eb.z))));
            const float a3 = fmaf(T.x, W3.x, fmaf(T.y, W3.y, fmaf(Bt.x, W3.z, fmaf(Bt.y, W3.w, eb.w))));

            const float ca0  = __cosf(a0);
            const float ca1q = __cosf(a1 + Kq1);
            float sa2, ca2, sa3, ca3;
            __sincosf(a2, &sa2, &ca2);
            __sincosf(a3, &sa3, &ca3);

            float e0 = Kc0 * ca0;
            float e1 = e0 * ca1q;
            float e2 = e1 * fmaf(c4, ca2, -Ks4 * sa2 * sa3);
            float e3 = ca2 * (Kc3 * ca3);
            if (tail && !tl) { e0 = 0.f; e1 = 0.f; e2 = 0.f; e3 = 0.f; }

            if (im) { PACK_F32X2(E01B, e0, e1); PACK_F32X2(E23B, e2, e3); }
            else    { PACK_F32X2(E01A, e0, e1); PACK_F32X2(E23A, e2, e3); }
        }

        // GEMV for this round: one weight load feeds both images
#pragma unroll
        for (int c = 0; c < 10; c++) {
            const double2 wd = __ldg(&lw2[c * NPATCH + p]);
            const unsigned long long wxy = __double_as_longlong(wd.x);
            const unsigned long long wzw = __double_as_longlong(wd.y);
            FMA_F32X2(acc2A[c], E23A, wzw, acc2A[c]);
            FMA_F32X2(acc2A[c], E01A, wxy, acc2A[c]);
            FMA_F32X2(acc2B[c], E23B, wzw, acc2B[c]);
            FMA_F32X2(acc2B[c], E01B, wxy, acc2B[c]);
        }
    }

    // ---- collapse packed pairs ----
    float aA[10], aB[10];
#pragma unroll
    for (int c = 0; c < 10; c++) {
        float lo, hi;
        UNPACK_F32X2(lo, hi, acc2A[c]); aA[c] = lo + hi;
        UNPACK_F32X2(lo, hi, acc2B[c]); aB[c] = lo + hi;
    }

    // ---- xor-butterfly both images' partials ----
#pragma unroll
    for (int off = 16; off > 0; off >>= 1)
#pragma unroll
        for (int c = 0; c < 10; c++) {
            aA[c] += __shfl_xor_sync(0xffffffffu, aA[c], off);
            aB[c] += __shfl_xor_sync(0xffffffffu, aB[c], off);
        }

    // handoff (predicated selection, no dynamic reg indexing)
    {
        float vAv = aA[0], vBv = aB[0];
#pragma unroll
        for (int c = 1; c < 10; c++) if (lane == c) { vAv = aA[c]; vBv = aB[c]; }
        if (lane < 10) {
            spart[pair][h][0][lane] = vAv;
            spart[pair][h][1][lane] = vBv;
        }
    }
    __syncthreads();

    // ---- finalize: warp h finishes image h of its pair (balanced) ----
    const int  bO = bA + h;
    const bool vO = (h == 0) ? vA : vB;
    if (lane < 10 && vO) {
        float lg[10];
#pragma unroll
        for (int c = 0; c < 10; c++)
            lg[c] = spart[pair][0][h][c] + spart[pair][1][h][c] + __ldg(&lin_b[c]);

        float mx = lg[0];
#pragma unroll
        for (int c = 1; c < 10; c++) mx = fmaxf(mx, lg[c]);
        float se = 0.f;
#pragma unroll
        for (int c = 0; c < 10; c++) se += __expf(lg[c] - mx);
        const float lse = mx + __logf(se);

        float v2 = lg[0];
#pragma unroll
        for (int c = 1; c < 10; c++) if (lane == c) v2 = lg[c];
        out[bO * 10 + lane] = v2 - lse;
    }
}

extern "C" void kernel_launch(void* const* d_in, const int* in_sizes, int n_in,
                              void* d_out, int out_size)
{
    const float* x        = (const float*)d_in[0];
    const float* emb_W    = (const float*)d_in[1];
    const float* emb_b    = (const float*)d_in[2];
    const float* q_params = (const float*)d_in[3];
    const float* lin_W    = (const float*)d_in[4];
    const float* lin_b    = (const float*)d_in[5];
    float* out = (float*)d_out;

    const int B = in_sizes[0] / 784;
    const int grid = (B + 3) / 4;
    quanv_fused_kernel<<<grid, BLOCK>>>(x, emb_W, emb_b, q_params, lin_W, lin_b, out, B);
}